// round 10
// baseline (speedup 1.0000x reference)
#include <cuda_runtime.h>
#include <cuda_fp16.h>
#include <cstdint>

#define BB 16
#define NN 25
#define WW 128
#define CH 256              // c*h
#define SS 3200             // n*w
#define BSTRIDE 819200
#define CSTRIDE 51200
#define NSTRIDE 2048
#define KCH 3               // K-split chunks in att (17/17/16 x 64)

// Scratch (device globals). Zero-init relied upon: g_att_part regions skipped
// by every launch stay 0 (softmax masks them anyway).
__device__ float g_att_part[KCH*BB*CH*CH];        // 12.6 MB partial logits
__device__ __half g_qh[BB*CH*SS];                 // normalized Q fp16 [row][s]
__device__ __half g_kh[BB*CH*SS];                 // normalized K fp16 [row][s]
__device__ __half g_vh[BB*CH*SS];                 // V fp16 [row][s]
__device__ __half g_ph[BB*CH*CH];                 // P fp16, zeros above diag

__device__ __forceinline__ int row_base(int b, int t) {
    return b*BSTRIDE + (t >> 4)*CSTRIDE + (t & 15)*WW;
}

#define SW128(x) ((x) ^ (((x) >> 3) & 0x70))
#define SW64(x)  ((x) ^ (((x) >> 3) & 0x30))

__device__ __forceinline__ uint32_t smem_u32(const void* p) {
    uint32_t a;
    asm("{ .reg .u64 t; cvta.to.shared.u64 t, %1; cvt.u32.u64 %0, t; }" : "=r"(a) : "l"(p));
    return a;
}
__device__ __forceinline__ void cp16(uint32_t dst, const void* src) {
    asm volatile("cp.async.cg.shared.global [%0], [%1], 16;"
                 :: "r"(dst), "l"(__cvta_generic_to_global(src)));
}
#define CP_COMMIT() asm volatile("cp.async.commit_group;" ::: "memory")
#define CP_WAIT0()  asm volatile("cp.async.wait_group 0;" ::: "memory")

__device__ __forceinline__ void ldsm_x4(uint32_t& r0, uint32_t& r1,
                                        uint32_t& r2, uint32_t& r3, uint32_t addr) {
    asm volatile("ldmatrix.sync.aligned.m8n8.x4.shared.b16 {%0,%1,%2,%3}, [%4];"
                 : "=r"(r0), "=r"(r1), "=r"(r2), "=r"(r3) : "r"(addr));
}
__device__ __forceinline__ void ldsm_x4t(uint32_t& r0, uint32_t& r1,
                                         uint32_t& r2, uint32_t& r3, uint32_t addr) {
    asm volatile("ldmatrix.sync.aligned.m8n8.x4.trans.shared.b16 {%0,%1,%2,%3}, [%4];"
                 : "=r"(r0), "=r"(r1), "=r"(r2), "=r"(r3) : "r"(addr));
}
__device__ __forceinline__ void mma16816(float* c, const uint32_t* a,
                                         uint32_t b0, uint32_t b1) {
    asm volatile(
        "mma.sync.aligned.m16n8k16.row.col.f32.f16.f16.f32 "
        "{%0,%1,%2,%3}, {%4,%5,%6,%7}, {%8,%9}, {%0,%1,%2,%3};"
        : "+f"(c[0]), "+f"(c[1]), "+f"(c[2]), "+f"(c[3])
        : "r"(a[0]), "r"(a[1]), "r"(a[2]), "r"(a[3]), "r"(b0), "r"(b1));
}
__device__ __forceinline__ uint32_t h2u(__half2 h) {
    return *reinterpret_cast<uint32_t*>(&h);
}

// One 64-wide K chunk, both operands SW128-swizzled [row][64 halves].
__device__ __forceinline__ void mma_chunk(uint32_t aSm, uint32_t bSm,
                                          int m0, int n0, int lane,
                                          float c[2][8][4]) {
    const int lar = lane & 15;
    const int lak = (lane >> 4) * 16;
    const int lbr = (lane & 7) | ((lane >> 4) << 3);
    const int lbk = ((lane >> 3) & 1) * 16;
    #pragma unroll
    for (int ks = 0; ks < 4; ++ks) {
        const int kb = ks * 32;
        uint32_t a[2][4];
        #pragma unroll
        for (int mt = 0; mt < 2; ++mt)
            ldsm_x4(a[mt][0], a[mt][1], a[mt][2], a[mt][3],
                    aSm + SW128((uint32_t)((m0 + mt*16 + lar)*128 + kb + lak)));
        #pragma unroll
        for (int np = 0; np < 4; ++np) {
            uint32_t b0, b1, b2, b3;
            ldsm_x4(b0, b1, b2, b3,
                    bSm + SW128((uint32_t)((n0 + np*16 + lbr)*128 + kb + lbk)));
            mma16816(c[0][np*2    ], a[0], b0, b1);
            mma16816(c[0][np*2 + 1], a[0], b2, b3);
            mma16816(c[1][np*2    ], a[1], b0, b1);
            mma16816(c[1][np*2 + 1], a[1], b2, b3);
        }
    }
}

// One 32-deep K chunk for out: A = P chunk [256 t][32 r halves] in 64B rows
// (SW64 swizzle); B = V chunk [32 r][64 s halves] natural, 144B row stride
// (conflict-free ldsm.trans). N fixed at 64 (np<4), n0 = 0.
#define VST2 144
__device__ __forceinline__ void mma_chunk32(uint32_t aSm, uint32_t vSm,
                                            int m0, int lane,
                                            float c[2][8][4]) {
    const int lar = lane & 15;
    const int lak = (lane >> 4) * 16;
    const int vr = lane & 15;
    const int vs = (lane >> 4) * 8;
    #pragma unroll
    for (int ks = 0; ks < 2; ++ks) {
        uint32_t a[2][4];
        #pragma unroll
        for (int mt = 0; mt < 2; ++mt)
            ldsm_x4(a[mt][0], a[mt][1], a[mt][2], a[mt][3],
                    aSm + SW64((uint32_t)((m0 + mt*16 + lar)*64 + ks*32 + lak)));
        #pragma unroll
        for (int np = 0; np < 4; ++np) {
            uint32_t b0, b1, b2, b3;
            ldsm_x4t(b0, b1, b2, b3,
                     vSm + (uint32_t)((ks*16 + vr)*VST2 + (np*16 + vs)*2));
            mma16816(c[0][np*2    ], a[0], b0, b1);
            mma16816(c[0][np*2 + 1], a[0], b2, b3);
            mma16816(c[1][np*2    ], a[1], b0, b1);
            mma16816(c[1][np*2 + 1], a[1], b2, b3);
        }
    }
}

// ---------------------------------------------------------------------------
// Kernel 1: fused L2-norm + normalize + fp16 pack for Q,K; fp16 convert of V.
// ---------------------------------------------------------------------------
__global__ __launch_bounds__(160) void prep_qk(const float* __restrict__ q,
                                               const float* __restrict__ k,
                                               const float* __restrict__ v) {
    __shared__ float rq[8], rk[8];
    const int row = blockIdx.x;
    const int b = row >> 8, t = row & 255;
    const int tid = threadIdx.x, lane = tid & 31, w = tid >> 5;
    const int base = row_base(b, t);
    float4 qv[5], kv[5];
    float sq = 0.f, sk = 0.f;
    #pragma unroll
    for (int g = 0; g < 5; ++g) {
        const int s = (tid + 160*g) * 4;
        const int a = base + (s >> 7)*NSTRIDE + (s & 127);
        qv[g] = *(const float4*)(q + a);
        kv[g] = *(const float4*)(k + a);
        sq += qv[g].x*qv[g].x + qv[g].y*qv[g].y + qv[g].z*qv[g].z + qv[g].w*qv[g].w;
        sk += kv[g].x*kv[g].x + kv[g].y*kv[g].y + kv[g].z*kv[g].z + kv[g].w*kv[g].w;
    }
    #pragma unroll
    for (int g = 0; g < 5; ++g) {
        const int s = (tid + 160*g) * 4;
        const int a = base + (s >> 7)*NSTRIDE + (s & 127);
        const float4 vv = *(const float4*)(v + a);
        uint2 uv;
        uv.x = h2u(__floats2half2_rn(vv.x, vv.y));
        uv.y = h2u(__floats2half2_rn(vv.z, vv.w));
        *(uint2*)(g_vh + (size_t)row*SS + s) = uv;
    }
    #pragma unroll
    for (int o = 16; o; o >>= 1) {
        sq += __shfl_xor_sync(0xffffffffu, sq, o);
        sk += __shfl_xor_sync(0xffffffffu, sk, o);
    }
    if (lane == 0) { rq[w] = sq; rk[w] = sk; }
    __syncthreads();
    sq = rq[0] + rq[1] + rq[2] + rq[3] + rq[4];
    sk = rk[0] + rk[1] + rk[2] + rk[3] + rk[4];
    const float iq = 1.f / fmaxf(sqrtf(sq), 1e-12f);
    const float ik = 1.f / fmaxf(sqrtf(sk), 1e-12f);
    #pragma unroll
    for (int g = 0; g < 5; ++g) {
        const int s = (tid + 160*g) * 4;
        uint2 uq, uk;
        uq.x = h2u(__floats2half2_rn(qv[g].x*iq, qv[g].y*iq));
        uq.y = h2u(__floats2half2_rn(qv[g].z*iq, qv[g].w*iq));
        uk.x = h2u(__floats2half2_rn(kv[g].x*ik, kv[g].y*ik));
        uk.y = h2u(__floats2half2_rn(kv[g].z*ik, kv[g].w*ik));
        *(uint2*)(g_qh + (size_t)row*SS + s) = uq;
        *(uint2*)(g_kh + (size_t)row*SS + s) = uk;
    }
}

// ---------------------------------------------------------------------------
// Kernel 2: att partial logits, cp.async double-buffered, fp16 mma.sync.
// CTA = (kc, b, tile), tile in {(mh0,nh0),(mh1,nh0),(mh1,nh1)}. Grid 144.
// Diagonal tiles: warps whose 64-col block is fully above the diagonal skip
// all mma (their zero accumulators are stored; softmax masks that region).
// ---------------------------------------------------------------------------
__global__ __launch_bounds__(256, 2) void att_mma() {
    extern __shared__ __align__(128) char sm[];
    int idx = blockIdx.x;
    const int kc = idx / 48; idx %= 48;
    const int b = idx / 3, tt = idx % 3;
    const int t0  = (tt > 0)  ? 128 : 0;
    const int n0c = (tt == 2) ? 128 : 0;
    const int nch = (kc == 2) ? 16 : 17;
    const int sb  = kc * 17 * 64;
    const int tid = threadIdx.x, lane = tid & 31, wid = tid >> 5;
    const int m0 = (wid & 3) * 32, n0w = (wid >> 2) * 64;
    const bool wskip = (t0 == n0c) && (n0w > m0 + 31);
    const uint32_t base = smem_u32(sm);

    float c[2][8][4];
    #pragma unroll
    for (int i = 0; i < 2; ++i)
        #pragma unroll
        for (int j = 0; j < 8; ++j)
            #pragma unroll
            for (int e = 0; e < 4; ++e) c[i][j][e] = 0.f;

    const int row = tid >> 1, hf = tid & 1;
    const __half* qp = g_qh + (size_t)(b*256 + t0  + row)*SS + sb + hf*32;
    const __half* kp = g_kh + (size_t)(b*256 + n0c + row)*SS + sb + hf*32;
    uint32_t so[4];
    #pragma unroll
    for (int g = 0; g < 4; ++g) so[g] = SW128((uint32_t)(row*128 + hf*64 + g*16));

    #pragma unroll
    for (int g = 0; g < 4; ++g) {
        cp16(base + so[g],         qp + g*8);
        cp16(base + 32768 + so[g], kp + g*8);
    }
    CP_COMMIT();

    for (int it = 0; it < nch; ++it) {
        CP_WAIT0();
        __syncthreads();
        const int nxt = it + 1;
        if (nxt < nch) {
            const uint32_t ab = base + (nxt & 1)*16384;
            #pragma unroll
            for (int g = 0; g < 4; ++g) {
                cp16(ab + so[g],         qp + nxt*64 + g*8);
                cp16(ab + 32768 + so[g], kp + nxt*64 + g*8);
            }
            CP_COMMIT();
        }
        if (!wskip) {
            const uint32_t cb = base + (it & 1)*16384;
            mma_chunk(cb, cb + 32768, m0, n0w, lane, c);
        }
    }

    float* dst = g_att_part + (size_t)kc*(4096*256) + (size_t)(b*256 + t0)*256;
    const int r0 = m0 + (lane >> 2);
    const int c0 = n0c + n0w + (lane & 3)*2;
    #pragma unroll
    for (int mt = 0; mt < 2; ++mt)
        #pragma unroll
        for (int n8 = 0; n8 < 8; ++n8) {
            float* p = dst + (size_t)(r0 + mt*16)*256 + c0 + n8*8;
            *(float2*)p           = make_float2(c[mt][n8][0], c[mt][n8][1]);
            *(float2*)(p + 8*256) = make_float2(c[mt][n8][2], c[mt][n8][3]);
        }
}

// ---------------------------------------------------------------------------
// Kernel 3: reduce partials (float4 vectorized), mask, softmax, emit P fp16.
// ---------------------------------------------------------------------------
__global__ __launch_bounds__(256) void softmax_kernel() {
    const int wid = threadIdx.x >> 5, lane = threadIdx.x & 31;
    const int row = blockIdx.x*8 + wid;   // b*256 + t
    const int t = row & 255;
    float4 a[2];
    #pragma unroll
    for (int j2 = 0; j2 < 2; ++j2) {
        float4 s = make_float4(0.f, 0.f, 0.f, 0.f);
        #pragma unroll
        for (int p = 0; p < KCH; ++p) {
            const float4 d = *(const float4*)(g_att_part + (size_t)p*(4096*256)
                                              + (size_t)row*256 + (j2*32 + lane)*4);
            s.x += d.x; s.y += d.y; s.z += d.z; s.w += d.w;
        }
        a[j2] = s;
    }
    float m = -1e30f;
    #pragma unroll
    for (int j2 = 0; j2 < 2; ++j2) {
        const int c0 = (j2*32 + lane)*4;
        float* e = &a[j2].x;
        #pragma unroll
        for (int q = 0; q < 4; ++q) {
            e[q] = (c0 + q <= t) ? e[q] : -1e30f;
            m = fmaxf(m, e[q]);
        }
    }
    #pragma unroll
    for (int o = 16; o; o >>= 1) m = fmaxf(m, __shfl_xor_sync(0xffffffffu, m, o));
    float ssum = 0.f;
    #pragma unroll
    for (int j2 = 0; j2 < 2; ++j2) {
        const int c0 = (j2*32 + lane)*4;
        float* e = &a[j2].x;
        #pragma unroll
        for (int q = 0; q < 4; ++q) {
            e[q] = (c0 + q <= t) ? __expf(e[q] - m) : 0.f;
            ssum += e[q];
        }
    }
    #pragma unroll
    for (int o = 16; o; o >>= 1) ssum += __shfl_xor_sync(0xffffffffu, ssum, o);
    const float inv = 1.f / ssum;
    #pragma unroll
    for (int j2 = 0; j2 < 2; ++j2) {
        uint2 u;
        u.x = h2u(__floats2half2_rn(a[j2].x*inv, a[j2].y*inv));
        u.y = h2u(__floats2half2_rn(a[j2].z*inv, a[j2].w*inv));
        *(uint2*)(g_ph + (size_t)row*256 + (j2*32 + lane)*4) = u;
    }
}

// ---------------------------------------------------------------------------
// Kernel 4: out = P @ V^T + buffer. CTA = (b, st): M=256 t, N=64 s,
// K=256 in 8 chunks of 32. 256 threads, 8 m-warps; warp m-tile map
// {0,1,2,3,7,6,5,4} balances per-SMSP work; warp wm runs chunks ic<=wm only
// (P zero beyond -> exact). Double-buffered cp.async; 2 CTAs/SM. Grid 800.
// smem: P0 P1 (16KB each, SW64 64B rows) | V0 V1 (4608B each). 41984 B.
// ---------------------------------------------------------------------------
#define OFF_OV0 32768u
#define OVB 4608u
__global__ __launch_bounds__(256, 2) void out_mma(const float* __restrict__ v,
                                                  float* __restrict__ out) {
    extern __shared__ __align__(128) char sm[];
    const int b = blockIdx.x / 50, st = blockIdx.x % 50;
    const int s0 = st * 64;
    const int tid = threadIdx.x, lane = tid & 31, wid = tid >> 5;
    const int wm = (wid & 4) ? (7 - (wid & 3)) : (wid & 3);
    const int m0 = wm * 32;
    const uint32_t base = smem_u32(sm);

    float c[2][8][4];
    #pragma unroll
    for (int i = 0; i < 2; ++i)
        #pragma unroll
        for (int j = 0; j < 8; ++j)
            #pragma unroll
            for (int e = 0; e < 4; ++e) c[i][j][e] = 0.f;

    // P staging: thread = one t-row (0..255), 64B per chunk = 4 cp16
    const __half* ap = g_ph + (size_t)(b*256 + tid)*256;
    uint32_t soP[4];
    #pragma unroll
    for (int g = 0; g < 4; ++g) soP[g] = SW64((uint32_t)(tid*64 + g*16));

    // V staging: vrow = tid/8 (0..31), seg = tid&7 (one 16B each)
    const int vrow = tid >> 3, seg = tid & 7;
    const __half* vp = g_vh + (size_t)(b*256 + vrow)*SS + s0 + seg*8;
    const uint32_t soV = (uint32_t)(vrow*VST2 + seg*16);

    // prologue: chunk 0
    #pragma unroll
    for (int g = 0; g < 4; ++g) cp16(base + soP[g], ap + g*8);
    cp16(base + OFF_OV0 + soV, vp);
    CP_COMMIT();

    #pragma unroll
    for (int ic = 0; ic < 8; ++ic) {
        CP_WAIT0();
        __syncthreads();
        const int nxt = ic + 1;
        if (nxt < 8) {
            const uint32_t pb = base + (uint32_t)(nxt & 1)*16384u;
            #pragma unroll
            for (int g = 0; g < 4; ++g) cp16(pb + soP[g], ap + nxt*32 + g*8);
            cp16(base + OFF_OV0 + (uint32_t)(nxt & 1)*OVB + soV,
                 vp + (size_t)nxt*32*SS);
            CP_COMMIT();
        }
        if (ic <= wm)
            mma_chunk32(base + (uint32_t)(ic & 1)*16384u,
                        base + OFF_OV0 + (uint32_t)(ic & 1)*OVB, m0, lane, c);
    }

    const int r0 = m0 + (lane >> 2);
    const int sc0 = (lane & 3)*2;
    const int soff = (s0 >> 7)*NSTRIDE + (s0 & 127);
    #pragma unroll
    for (int mt = 0; mt < 2; ++mt) {
        const int tA = r0 + mt*16;
        const int gA = row_base(b, tA)     + soff;
        const int gB = row_base(b, tA + 8) + soff;
        #pragma unroll
        for (int n8 = 0; n8 < 8; ++n8) {
            const int sc = sc0 + n8*8;
            const float2 buA = *(const float2*)(v + gA + sc);
            const float2 buB = *(const float2*)(v + gB + sc);
            *(float2*)(out + gA + sc) =
                make_float2(c[mt][n8][0] + buA.x, c[mt][n8][1] + buA.y);
            *(float2*)(out + gB + sc) =
                make_float2(c[mt][n8][2] + buB.x, c[mt][n8][3] + buB.y);
        }
    }
}

// ---------------------------------------------------------------------------
#define ATT_SMEM 65536
#define OUT_SMEM 41984

extern "C" void kernel_launch(void* const* d_in, const int* in_sizes, int n_in,
                              void* d_out, int out_size) {
    const float* q = (const float*)d_in[0];
    const float* k = (const float*)d_in[1];
    const float* v = (const float*)d_in[2];
    float* out = (float*)d_out;

    cudaFuncSetAttribute(att_mma, cudaFuncAttributeMaxDynamicSharedMemorySize, ATT_SMEM);
    cudaFuncSetAttribute(out_mma, cudaFuncAttributeMaxDynamicSharedMemorySize, OUT_SMEM);

    prep_qk<<<BB*CH, 160>>>(q, k, v);
    att_mma<<<KCH*BB*3, 256, ATT_SMEM>>>();
    softmax_kernel<<<BB*CH/8, 256>>>();
    out_mma<<<BB*50, 256, OUT_SMEM>>>(v, out);
}

// round 11
// speedup vs baseline: 1.1024x; 1.1024x over previous
#include <cuda_runtime.h>
#include <cuda_fp16.h>
#include <cstdint>

#define BB 16
#define NN 25
#define WW 128
#define CH 256              // c*h
#define SS 3200             // n*w
#define BSTRIDE 819200
#define CSTRIDE 51200
#define NSTRIDE 2048
#define KCH 3               // K-split chunks in att (17/17/16 x 64)

// Scratch (device globals). Zero-init relied upon: g_att_part regions skipped
// by every launch stay 0 (softmax masks them anyway).
__device__ float g_att_part[KCH*BB*CH*CH];        // 12.6 MB partial logits
__device__ __half g_qh[BB*CH*SS];                 // normalized Q fp16 [row][s]
__device__ __half g_kh[BB*CH*SS];                 // normalized K fp16 [row][s]
__device__ __half g_vh[BB*CH*SS];                 // V fp16 [row][s]
__device__ __half g_ph[BB*CH*CH];                 // P fp16, zeros above diag

__device__ __forceinline__ int row_base(int b, int t) {
    return b*BSTRIDE + (t >> 4)*CSTRIDE + (t & 15)*WW;
}

#define SW128(x) ((x) ^ (((x) >> 3) & 0x70))

__device__ __forceinline__ uint32_t smem_u32(const void* p) {
    uint32_t a;
    asm("{ .reg .u64 t; cvta.to.shared.u64 t, %1; cvt.u32.u64 %0, t; }" : "=r"(a) : "l"(p));
    return a;
}
__device__ __forceinline__ void cp16(uint32_t dst, const void* src) {
    asm volatile("cp.async.cg.shared.global [%0], [%1], 16;"
                 :: "r"(dst), "l"(__cvta_generic_to_global(src)));
}
#define CP_COMMIT() asm volatile("cp.async.commit_group;" ::: "memory")
#define CP_WAIT0()  asm volatile("cp.async.wait_group 0;" ::: "memory")

__device__ __forceinline__ void ldsm_x4(uint32_t& r0, uint32_t& r1,
                                        uint32_t& r2, uint32_t& r3, uint32_t addr) {
    asm volatile("ldmatrix.sync.aligned.m8n8.x4.shared.b16 {%0,%1,%2,%3}, [%4];"
                 : "=r"(r0), "=r"(r1), "=r"(r2), "=r"(r3) : "r"(addr));
}
__device__ __forceinline__ void ldsm_x4t(uint32_t& r0, uint32_t& r1,
                                         uint32_t& r2, uint32_t& r3, uint32_t addr) {
    asm volatile("ldmatrix.sync.aligned.m8n8.x4.trans.shared.b16 {%0,%1,%2,%3}, [%4];"
                 : "=r"(r0), "=r"(r1), "=r"(r2), "=r"(r3) : "r"(addr));
}
__device__ __forceinline__ void mma16816(float* c, const uint32_t* a,
                                         uint32_t b0, uint32_t b1) {
    asm volatile(
        "mma.sync.aligned.m16n8k16.row.col.f32.f16.f16.f32 "
        "{%0,%1,%2,%3}, {%4,%5,%6,%7}, {%8,%9}, {%0,%1,%2,%3};"
        : "+f"(c[0]), "+f"(c[1]), "+f"(c[2]), "+f"(c[3])
        : "r"(a[0]), "r"(a[1]), "r"(a[2]), "r"(a[3]), "r"(b0), "r"(b1));
}
__device__ __forceinline__ uint32_t h2u(__half2 h) {
    return *reinterpret_cast<uint32_t*>(&h);
}

// One 64-wide K chunk, both operands SW128-swizzled [row][64 halves].
__device__ __forceinline__ void mma_chunk(uint32_t aSm, uint32_t bSm,
                                          int m0, int n0, int lane,
                                          float c[2][8][4]) {
    const int lar = lane & 15;
    const int lak = (lane >> 4) * 16;
    const int lbr = (lane & 7) | ((lane >> 4) << 3);
    const int lbk = ((lane >> 3) & 1) * 16;
    #pragma unroll
    for (int ks = 0; ks < 4; ++ks) {
        const int kb = ks * 32;
        uint32_t a[2][4];
        #pragma unroll
        for (int mt = 0; mt < 2; ++mt)
            ldsm_x4(a[mt][0], a[mt][1], a[mt][2], a[mt][3],
                    aSm + SW128((uint32_t)((m0 + mt*16 + lar)*128 + kb + lak)));
        #pragma unroll
        for (int np = 0; np < 4; ++np) {
            uint32_t b0, b1, b2, b3;
            ldsm_x4(b0, b1, b2, b3,
                    bSm + SW128((uint32_t)((n0 + np*16 + lbr)*128 + kb + lbk)));
            mma16816(c[0][np*2    ], a[0], b0, b1);
            mma16816(c[0][np*2 + 1], a[0], b2, b3);
            mma16816(c[1][np*2    ], a[1], b0, b1);
            mma16816(c[1][np*2 + 1], a[1], b2, b3);
        }
    }
}

// One 64-deep K chunk; A = P chunk (SW128 128B rows), B = V chunk natural
// [r=k 64 rows][s=n 128 halves], 272B row stride (conflict-free ldsm.trans).
#define VSTR 136
__device__ __forceinline__ void mma_chunk_bt(uint32_t aSm, uint32_t vSm,
                                             int m0, int n0, int lane,
                                             float c[2][8][4]) {
    const int lar = lane & 15;
    const int lak = (lane >> 4) * 16;
    const int vr = lane & 15;
    const int vs = (lane >> 4) * 8;
    #pragma unroll
    for (int ks = 0; ks < 4; ++ks) {
        uint32_t a[2][4];
        #pragma unroll
        for (int mt = 0; mt < 2; ++mt)
            ldsm_x4(a[mt][0], a[mt][1], a[mt][2], a[mt][3],
                    aSm + SW128((uint32_t)((m0 + mt*16 + lar)*128 + ks*32 + lak)));
        #pragma unroll
        for (int np = 0; np < 4; ++np) {
            uint32_t b0, b1, b2, b3;
            ldsm_x4t(b0, b1, b2, b3,
                     vSm + (uint32_t)((ks*16 + vr)*(VSTR*2) + (n0 + np*16 + vs)*2));
            mma16816(c[0][np*2    ], a[0], b0, b1);
            mma16816(c[0][np*2 + 1], a[0], b2, b3);
            mma16816(c[1][np*2    ], a[1], b0, b1);
            mma16816(c[1][np*2 + 1], a[1], b2, b3);
        }
    }
}

// ---------------------------------------------------------------------------
// Kernel 1: fused L2-norm + normalize + fp16 pack for Q,K; fp16 convert of V.
// ---------------------------------------------------------------------------
__global__ __launch_bounds__(160) void prep_qk(const float* __restrict__ q,
                                               const float* __restrict__ k,
                                               const float* __restrict__ v) {
    __shared__ float rq[8], rk[8];
    const int row = blockIdx.x;
    const int b = row >> 8, t = row & 255;
    const int tid = threadIdx.x, lane = tid & 31, w = tid >> 5;
    const int base = row_base(b, t);
    float4 qv[5], kv[5];
    float sq = 0.f, sk = 0.f;
    #pragma unroll
    for (int g = 0; g < 5; ++g) {
        const int s = (tid + 160*g) * 4;
        const int a = base + (s >> 7)*NSTRIDE + (s & 127);
        qv[g] = *(const float4*)(q + a);
        kv[g] = *(const float4*)(k + a);
        sq += qv[g].x*qv[g].x + qv[g].y*qv[g].y + qv[g].z*qv[g].z + qv[g].w*qv[g].w;
        sk += kv[g].x*kv[g].x + kv[g].y*kv[g].y + kv[g].z*kv[g].z + kv[g].w*kv[g].w;
    }
    #pragma unroll
    for (int g = 0; g < 5; ++g) {
        const int s = (tid + 160*g) * 4;
        const int a = base + (s >> 7)*NSTRIDE + (s & 127);
        const float4 vv = *(const float4*)(v + a);
        uint2 uv;
        uv.x = h2u(__floats2half2_rn(vv.x, vv.y));
        uv.y = h2u(__floats2half2_rn(vv.z, vv.w));
        *(uint2*)(g_vh + (size_t)row*SS + s) = uv;
    }
    #pragma unroll
    for (int o = 16; o; o >>= 1) {
        sq += __shfl_xor_sync(0xffffffffu, sq, o);
        sk += __shfl_xor_sync(0xffffffffu, sk, o);
    }
    if (lane == 0) { rq[w] = sq; rk[w] = sk; }
    __syncthreads();
    sq = rq[0] + rq[1] + rq[2] + rq[3] + rq[4];
    sk = rk[0] + rk[1] + rk[2] + rk[3] + rk[4];
    const float iq = 1.f / fmaxf(sqrtf(sq), 1e-12f);
    const float ik = 1.f / fmaxf(sqrtf(sk), 1e-12f);
    #pragma unroll
    for (int g = 0; g < 5; ++g) {
        const int s = (tid + 160*g) * 4;
        uint2 uq, uk;
        uq.x = h2u(__floats2half2_rn(qv[g].x*iq, qv[g].y*iq));
        uq.y = h2u(__floats2half2_rn(qv[g].z*iq, qv[g].w*iq));
        uk.x = h2u(__floats2half2_rn(kv[g].x*ik, kv[g].y*ik));
        uk.y = h2u(__floats2half2_rn(kv[g].z*ik, kv[g].w*ik));
        *(uint2*)(g_qh + (size_t)row*SS + s) = uq;
        *(uint2*)(g_kh + (size_t)row*SS + s) = uk;
    }
}

// ---------------------------------------------------------------------------
// Kernel 2: att partial logits, cp.async double-buffered, fp16 mma.sync.
// CTA = (kc, b, tile), tile in {(mh0,nh0),(mh1,nh0),(mh1,nh1)}. Grid 144.
// Diagonal tiles: warps fully above the diagonal skip all mma (zeros stored;
// softmax masks that region).
// ---------------------------------------------------------------------------
__global__ __launch_bounds__(256, 2) void att_mma() {
    extern __shared__ __align__(128) char sm[];
    int idx = blockIdx.x;
    const int kc = idx / 48; idx %= 48;
    const int b = idx / 3, tt = idx % 3;
    const int t0  = (tt > 0)  ? 128 : 0;
    const int n0c = (tt == 2) ? 128 : 0;
    const int nch = (kc == 2) ? 16 : 17;
    const int sb  = kc * 17 * 64;
    const int tid = threadIdx.x, lane = tid & 31, wid = tid >> 5;
    const int m0 = (wid & 3) * 32, n0w = (wid >> 2) * 64;
    const bool wskip = (t0 == n0c) && (n0w > m0 + 31);
    const uint32_t base = smem_u32(sm);

    float c[2][8][4];
    #pragma unroll
    for (int i = 0; i < 2; ++i)
        #pragma unroll
        for (int j = 0; j < 8; ++j)
            #pragma unroll
            for (int e = 0; e < 4; ++e) c[i][j][e] = 0.f;

    const int row = tid >> 1, hf = tid & 1;
    const __half* qp = g_qh + (size_t)(b*256 + t0  + row)*SS + sb + hf*32;
    const __half* kp = g_kh + (size_t)(b*256 + n0c + row)*SS + sb + hf*32;
    uint32_t so[4];
    #pragma unroll
    for (int g = 0; g < 4; ++g) so[g] = SW128((uint32_t)(row*128 + hf*64 + g*16));

    #pragma unroll
    for (int g = 0; g < 4; ++g) {
        cp16(base + so[g],         qp + g*8);
        cp16(base + 32768 + so[g], kp + g*8);
    }
    CP_COMMIT();

    for (int it = 0; it < nch; ++it) {
        CP_WAIT0();
        __syncthreads();
        const int nxt = it + 1;
        if (nxt < nch) {
            const uint32_t ab = base + (nxt & 1)*16384;
            #pragma unroll
            for (int g = 0; g < 4; ++g) {
                cp16(ab + so[g],         qp + nxt*64 + g*8);
                cp16(ab + 32768 + so[g], kp + nxt*64 + g*8);
            }
            CP_COMMIT();
        }
        if (!wskip) {
            const uint32_t cb = base + (it & 1)*16384;
            mma_chunk(cb, cb + 32768, m0, n0w, lane, c);
        }
    }

    float* dst = g_att_part + (size_t)kc*(4096*256) + (size_t)(b*256 + t0)*256;
    const int r0 = m0 + (lane >> 2);
    const int c0 = n0c + n0w + (lane & 3)*2;
    #pragma unroll
    for (int mt = 0; mt < 2; ++mt)
        #pragma unroll
        for (int n8 = 0; n8 < 8; ++n8) {
            float* p = dst + (size_t)(r0 + mt*16)*256 + c0 + n8*8;
            *(float2*)p           = make_float2(c[mt][n8][0], c[mt][n8][1]);
            *(float2*)(p + 8*256) = make_float2(c[mt][n8][2], c[mt][n8][3]);
        }
}

// ---------------------------------------------------------------------------
// Kernel 3: reduce partials (float4 vectorized), mask, softmax, emit P fp16.
// ---------------------------------------------------------------------------
__global__ __launch_bounds__(256) void softmax_kernel() {
    const int wid = threadIdx.x >> 5, lane = threadIdx.x & 31;
    const int row = blockIdx.x*8 + wid;   // b*256 + t
    const int t = row & 255;
    float4 a[2];
    #pragma unroll
    for (int j2 = 0; j2 < 2; ++j2) {
        float4 s = make_float4(0.f, 0.f, 0.f, 0.f);
        #pragma unroll
        for (int p = 0; p < KCH; ++p) {
            const float4 d = *(const float4*)(g_att_part + (size_t)p*(4096*256)
                                              + (size_t)row*256 + (j2*32 + lane)*4);
            s.x += d.x; s.y += d.y; s.z += d.z; s.w += d.w;
        }
        a[j2] = s;
    }
    float m = -1e30f;
    #pragma unroll
    for (int j2 = 0; j2 < 2; ++j2) {
        const int c0 = (j2*32 + lane)*4;
        float* e = &a[j2].x;
        #pragma unroll
        for (int q = 0; q < 4; ++q) {
            e[q] = (c0 + q <= t) ? e[q] : -1e30f;
            m = fmaxf(m, e[q]);
        }
    }
    #pragma unroll
    for (int o = 16; o; o >>= 1) m = fmaxf(m, __shfl_xor_sync(0xffffffffu, m, o));
    float ssum = 0.f;
    #pragma unroll
    for (int j2 = 0; j2 < 2; ++j2) {
        const int c0 = (j2*32 + lane)*4;
        float* e = &a[j2].x;
        #pragma unroll
        for (int q = 0; q < 4; ++q) {
            e[q] = (c0 + q <= t) ? __expf(e[q] - m) : 0.f;
            ssum += e[q];
        }
    }
    #pragma unroll
    for (int o = 16; o; o >>= 1) ssum += __shfl_xor_sync(0xffffffffu, ssum, o);
    const float inv = 1.f / ssum;
    #pragma unroll
    for (int j2 = 0; j2 < 2; ++j2) {
        uint2 u;
        u.x = h2u(__floats2half2_rn(a[j2].x*inv, a[j2].y*inv));
        u.y = h2u(__floats2half2_rn(a[j2].z*inv, a[j2].w*inv));
        *(uint2*)(g_ph + (size_t)row*256 + (j2*32 + lane)*4) = u;
    }
}

// ---------------------------------------------------------------------------
// Kernel 4: out = P @ V^T + buffer. CTA = (b, st): M=256 t, N=128 s, K=256.
// ALL operands (P 128KB + V 68KB) loaded to smem in ONE cp.async burst ->
// zero mainloop barriers. Warp map wm={0,1,2,3,7,6,5,4}[wid&7] (balanced
// per-SMSP); warp wm runs only chunks ic < wm/2+1 (P zero beyond -> exact)
// and simply finishes early. 512 threads, grid 400.
// smem: P[4]x32KB | V[4]x17408B = 200704 B.
// ---------------------------------------------------------------------------
#define OPB 32768u
#define OVB 17408u
#define OFF_V 131072u
__global__ __launch_bounds__(512) void out_mma(const float* __restrict__ v,
                                               float* __restrict__ out) {
    extern __shared__ __align__(128) char sm[];
    const int b = blockIdx.x / 25, st = blockIdx.x % 25;
    const int tid = threadIdx.x, lane = tid & 31, wid = tid >> 5;
    const int w7 = wid & 7;
    const int wm = (w7 < 4) ? w7 : (11 - w7);     // {0,1,2,3,7,6,5,4}
    const int m0 = wm * 32, n0w = (wid >> 3) * 64;
    const int nc = wm/2 + 1;                      // causal chunk bound
    const uint32_t base = smem_u32(sm);

    float c[2][8][4];
    #pragma unroll
    for (int i = 0; i < 2; ++i)
        #pragma unroll
        for (int j = 0; j < 8; ++j)
            #pragma unroll
            for (int e = 0; e < 4; ++e) c[i][j][e] = 0.f;

    // P: prow = tid/2 (0..255), half ph = tid&1; 4 cp16 per chunk
    const int prow = tid >> 1, ph = tid & 1;
    const __half* ap = g_ph + (size_t)(b*256 + prow)*256 + ph*32;
    uint32_t soP[4];
    #pragma unroll
    for (int g = 0; g < 4; ++g) soP[g] = SW128((uint32_t)(prow*128 + ph*64 + g*16));

    // V: vrow = tid/8 (0..63), seg = tid&7; 2 cp16 per chunk
    const int vrow = tid >> 3, seg = tid & 7;
    const __half* vp = g_vh + (size_t)(b*256 + vrow)*SS + st*128 + seg*16;
    const uint32_t soV = (uint32_t)(vrow*(VSTR*2) + seg*32);

    // one burst: everything
    #pragma unroll
    for (int ic = 0; ic < 4; ++ic) {
        #pragma unroll
        for (int g = 0; g < 4; ++g)
            cp16(base + ic*OPB + soP[g], ap + ic*64 + g*8);
        const __half* vs = vp + (size_t)ic*64*SS;
        cp16(base + OFF_V + ic*OVB + soV,      vs);
        cp16(base + OFF_V + ic*OVB + soV + 16, vs + 8);
    }
    CP_COMMIT();
    CP_WAIT0();
    __syncthreads();

    // barrier-free mainloop; warps finish early per causal bound
    for (int ic = 0; ic < nc; ++ic)
        mma_chunk_bt(base + (uint32_t)ic*OPB,
                     base + OFF_V + (uint32_t)ic*OVB, m0, n0w, lane, c);

    const int r0 = m0 + (lane >> 2);
    const int sc0 = n0w + (lane & 3)*2;
    const int soff = st*NSTRIDE;
    #pragma unroll
    for (int mt = 0; mt < 2; ++mt) {
        const int tA = r0 + mt*16;
        const int gA = row_base(b, tA)     + soff;
        const int gB = row_base(b, tA + 8) + soff;
        #pragma unroll
        for (int n8 = 0; n8 < 8; ++n8) {
            const int sc = sc0 + n8*8;
            const float2 buA = *(const float2*)(v + gA + sc);
            const float2 buB = *(const float2*)(v + gB + sc);
            *(float2*)(out + gA + sc) =
                make_float2(c[mt][n8][0] + buA.x, c[mt][n8][1] + buA.y);
            *(float2*)(out + gB + sc) =
                make_float2(c[mt][n8][2] + buB.x, c[mt][n8][3] + buB.y);
        }
    }
}

// ---------------------------------------------------------------------------
#define ATT_SMEM 65536
#define OUT_SMEM 200704

extern "C" void kernel_launch(void* const* d_in, const int* in_sizes, int n_in,
                              void* d_out, int out_size) {
    const float* q = (const float*)d_in[0];
    const float* k = (const float*)d_in[1];
    const float* v = (const float*)d_in[2];
    float* out = (float*)d_out;

    cudaFuncSetAttribute(att_mma, cudaFuncAttributeMaxDynamicSharedMemorySize, ATT_SMEM);
    cudaFuncSetAttribute(out_mma, cudaFuncAttributeMaxDynamicSharedMemorySize, OUT_SMEM);

    prep_qk<<<BB*CH, 160>>>(q, k, v);
    att_mma<<<KCH*BB*3, 256, ATT_SMEM>>>();
    softmax_kernel<<<BB*CH/8, 256>>>();
    out_mma<<<BB*NN, 512, OUT_SMEM>>>(v, out);
}

// round 12
// speedup vs baseline: 1.2339x; 1.1193x over previous
#include <cuda_runtime.h>
#include <cuda_fp16.h>
#include <cstdint>

#define BB 16
#define NN 25
#define WW 128
#define CH 256              // c*h
#define SS 3200             // n*w
#define BSTRIDE 819200
#define CSTRIDE 51200
#define NSTRIDE 2048
#define KCH 3               // K-split chunks in att (17/17/16 x 64)

// Scratch (device globals). Zero-init relied upon: g_att_part regions skipped
// by every launch stay 0 (softmax masks them anyway).
__device__ float g_att_part[KCH*BB*CH*CH];        // 12.6 MB partial logits
__device__ __half g_qh[BB*CH*SS];                 // normalized Q fp16 [row][s]
__device__ __half g_kh[BB*CH*SS];                 // normalized K fp16 [row][s]
__device__ __half g_vh[BB*CH*SS];                 // V fp16 [row][s]
__device__ __half g_ph[BB*CH*CH];                 // P + I (fp16), zeros above diag

__device__ __forceinline__ int row_base(int b, int t) {
    return b*BSTRIDE + (t >> 4)*CSTRIDE + (t & 15)*WW;
}

#define SW128(x) ((x) ^ (((x) >> 3) & 0x70))

__device__ __forceinline__ uint32_t smem_u32(const void* p) {
    uint32_t a;
    asm("{ .reg .u64 t; cvta.to.shared.u64 t, %1; cvt.u32.u64 %0, t; }" : "=r"(a) : "l"(p));
    return a;
}
__device__ __forceinline__ void cp16(uint32_t dst, const void* src) {
    asm volatile("cp.async.cg.shared.global [%0], [%1], 16;"
                 :: "r"(dst), "l"(__cvta_generic_to_global(src)));
}
#define CP_COMMIT() asm volatile("cp.async.commit_group;" ::: "memory")
#define CP_WAIT0()  asm volatile("cp.async.wait_group 0;" ::: "memory")

__device__ __forceinline__ void ldsm_x4(uint32_t& r0, uint32_t& r1,
                                        uint32_t& r2, uint32_t& r3, uint32_t addr) {
    asm volatile("ldmatrix.sync.aligned.m8n8.x4.shared.b16 {%0,%1,%2,%3}, [%4];"
                 : "=r"(r0), "=r"(r1), "=r"(r2), "=r"(r3) : "r"(addr));
}
__device__ __forceinline__ void ldsm_x4t(uint32_t& r0, uint32_t& r1,
                                         uint32_t& r2, uint32_t& r3, uint32_t addr) {
    asm volatile("ldmatrix.sync.aligned.m8n8.x4.trans.shared.b16 {%0,%1,%2,%3}, [%4];"
                 : "=r"(r0), "=r"(r1), "=r"(r2), "=r"(r3) : "r"(addr));
}
__device__ __forceinline__ void mma16816(float* c, const uint32_t* a,
                                         uint32_t b0, uint32_t b1) {
    asm volatile(
        "mma.sync.aligned.m16n8k16.row.col.f32.f16.f16.f32 "
        "{%0,%1,%2,%3}, {%4,%5,%6,%7}, {%8,%9}, {%0,%1,%2,%3};"
        : "+f"(c[0]), "+f"(c[1]), "+f"(c[2]), "+f"(c[3])
        : "r"(a[0]), "r"(a[1]), "r"(a[2]), "r"(a[3]), "r"(b0), "r"(b1));
}
__device__ __forceinline__ uint32_t h2u(__half2 h) {
    return *reinterpret_cast<uint32_t*>(&h);
}

// One 64-wide K chunk, both operands SW128-swizzled [row][64 halves].
__device__ __forceinline__ void mma_chunk(uint32_t aSm, uint32_t bSm,
                                          int m0, int n0, int lane,
                                          float c[2][8][4]) {
    const int lar = lane & 15;
    const int lak = (lane >> 4) * 16;
    const int lbr = (lane & 7) | ((lane >> 4) << 3);
    const int lbk = ((lane >> 3) & 1) * 16;
    #pragma unroll
    for (int ks = 0; ks < 4; ++ks) {
        const int kb = ks * 32;
        uint32_t a[2][4];
        #pragma unroll
        for (int mt = 0; mt < 2; ++mt)
            ldsm_x4(a[mt][0], a[mt][1], a[mt][2], a[mt][3],
                    aSm + SW128((uint32_t)((m0 + mt*16 + lar)*128 + kb + lak)));
        #pragma unroll
        for (int np = 0; np < 4; ++np) {
            uint32_t b0, b1, b2, b3;
            ldsm_x4(b0, b1, b2, b3,
                    bSm + SW128((uint32_t)((n0 + np*16 + lbr)*128 + kb + lbk)));
            mma16816(c[0][np*2    ], a[0], b0, b1);
            mma16816(c[0][np*2 + 1], a[0], b2, b3);
            mma16816(c[1][np*2    ], a[1], b0, b1);
            mma16816(c[1][np*2 + 1], a[1], b2, b3);
        }
    }
}

// One 64-deep K chunk; A = P chunk (SW128 128B rows), B = V chunk natural
// [r=k 64 rows][s=n 128 halves], 272B row stride (conflict-free ldsm.trans).
#define VSTR 136
__device__ __forceinline__ void mma_chunk_bt(uint32_t aSm, uint32_t vSm,
                                             int m0, int n0, int lane,
                                             float c[2][8][4]) {
    const int lar = lane & 15;
    const int lak = (lane >> 4) * 16;
    const int vr = lane & 15;
    const int vs = (lane >> 4) * 8;
    #pragma unroll
    for (int ks = 0; ks < 4; ++ks) {
        uint32_t a[2][4];
        #pragma unroll
        for (int mt = 0; mt < 2; ++mt)
            ldsm_x4(a[mt][0], a[mt][1], a[mt][2], a[mt][3],
                    aSm + SW128((uint32_t)((m0 + mt*16 + lar)*128 + ks*32 + lak)));
        #pragma unroll
        for (int np = 0; np < 4; ++np) {
            uint32_t b0, b1, b2, b3;
            ldsm_x4t(b0, b1, b2, b3,
                     vSm + (uint32_t)((ks*16 + vr)*(VSTR*2) + (n0 + np*16 + vs)*2));
            mma16816(c[0][np*2    ], a[0], b0, b1);
            mma16816(c[0][np*2 + 1], a[0], b2, b3);
            mma16816(c[1][np*2    ], a[1], b0, b1);
            mma16816(c[1][np*2 + 1], a[1], b2, b3);
        }
    }
}

// ---------------------------------------------------------------------------
// Kernel 1: fused L2-norm + normalize + fp16 pack for Q,K; fp16 convert of V.
// ---------------------------------------------------------------------------
__global__ __launch_bounds__(160) void prep_qk(const float* __restrict__ q,
                                               const float* __restrict__ k,
                                               const float* __restrict__ v) {
    __shared__ float rq[8], rk[8];
    const int row = blockIdx.x;
    const int b = row >> 8, t = row & 255;
    const int tid = threadIdx.x, lane = tid & 31, w = tid >> 5;
    const int base = row_base(b, t);
    float4 qv[5], kv[5];
    float sq = 0.f, sk = 0.f;
    #pragma unroll
    for (int g = 0; g < 5; ++g) {
        const int s = (tid + 160*g) * 4;
        const int a = base + (s >> 7)*NSTRIDE + (s & 127);
        qv[g] = *(const float4*)(q + a);
        kv[g] = *(const float4*)(k + a);
        sq += qv[g].x*qv[g].x + qv[g].y*qv[g].y + qv[g].z*qv[g].z + qv[g].w*qv[g].w;
        sk += kv[g].x*kv[g].x + kv[g].y*kv[g].y + kv[g].z*kv[g].z + kv[g].w*kv[g].w;
    }
    #pragma unroll
    for (int g = 0; g < 5; ++g) {
        const int s = (tid + 160*g) * 4;
        const int a = base + (s >> 7)*NSTRIDE + (s & 127);
        const float4 vv = *(const float4*)(v + a);
        uint2 uv;
        uv.x = h2u(__floats2half2_rn(vv.x, vv.y));
        uv.y = h2u(__floats2half2_rn(vv.z, vv.w));
        *(uint2*)(g_vh + (size_t)row*SS + s) = uv;
    }
    #pragma unroll
    for (int o = 16; o; o >>= 1) {
        sq += __shfl_xor_sync(0xffffffffu, sq, o);
        sk += __shfl_xor_sync(0xffffffffu, sk, o);
    }
    if (lane == 0) { rq[w] = sq; rk[w] = sk; }
    __syncthreads();
    sq = rq[0] + rq[1] + rq[2] + rq[3] + rq[4];
    sk = rk[0] + rk[1] + rk[2] + rk[3] + rk[4];
    const float iq = 1.f / fmaxf(sqrtf(sq), 1e-12f);
    const float ik = 1.f / fmaxf(sqrtf(sk), 1e-12f);
    #pragma unroll
    for (int g = 0; g < 5; ++g) {
        const int s = (tid + 160*g) * 4;
        uint2 uq, uk;
        uq.x = h2u(__floats2half2_rn(qv[g].x*iq, qv[g].y*iq));
        uq.y = h2u(__floats2half2_rn(qv[g].z*iq, qv[g].w*iq));
        uk.x = h2u(__floats2half2_rn(kv[g].x*ik, kv[g].y*ik));
        uk.y = h2u(__floats2half2_rn(kv[g].z*ik, kv[g].w*ik));
        *(uint2*)(g_qh + (size_t)row*SS + s) = uq;
        *(uint2*)(g_kh + (size_t)row*SS + s) = uk;
    }
}

// ---------------------------------------------------------------------------
// Kernel 2: att partial logits, cp.async double-buffered, fp16 mma.sync.
// CTA = (kc, b, tile), tile in {(mh0,nh0),(mh1,nh0),(mh1,nh1)}. Grid 144.
// Diagonal tiles: warps fully above the diagonal skip all mma (zeros stored;
// softmax masks that region).
// ---------------------------------------------------------------------------
__global__ __launch_bounds__(256, 2) void att_mma() {
    extern __shared__ __align__(128) char sm[];
    int idx = blockIdx.x;
    const int kc = idx / 48; idx %= 48;
    const int b = idx / 3, tt = idx % 3;
    const int t0  = (tt > 0)  ? 128 : 0;
    const int n0c = (tt == 2) ? 128 : 0;
    const int nch = (kc == 2) ? 16 : 17;
    const int sb  = kc * 17 * 64;
    const int tid = threadIdx.x, lane = tid & 31, wid = tid >> 5;
    const int m0 = (wid & 3) * 32, n0w = (wid >> 2) * 64;
    const bool wskip = (t0 == n0c) && (n0w > m0 + 31);
    const uint32_t base = smem_u32(sm);

    float c[2][8][4];
    #pragma unroll
    for (int i = 0; i < 2; ++i)
        #pragma unroll
        for (int j = 0; j < 8; ++j)
            #pragma unroll
            for (int e = 0; e < 4; ++e) c[i][j][e] = 0.f;

    const int row = tid >> 1, hf = tid & 1;
    const __half* qp = g_qh + (size_t)(b*256 + t0  + row)*SS + sb + hf*32;
    const __half* kp = g_kh + (size_t)(b*256 + n0c + row)*SS + sb + hf*32;
    uint32_t so[4];
    #pragma unroll
    for (int g = 0; g < 4; ++g) so[g] = SW128((uint32_t)(row*128 + hf*64 + g*16));

    #pragma unroll
    for (int g = 0; g < 4; ++g) {
        cp16(base + so[g],         qp + g*8);
        cp16(base + 32768 + so[g], kp + g*8);
    }
    CP_COMMIT();

    for (int it = 0; it < nch; ++it) {
        CP_WAIT0();
        __syncthreads();
        const int nxt = it + 1;
        if (nxt < nch) {
            const uint32_t ab = base + (nxt & 1)*16384;
            #pragma unroll
            for (int g = 0; g < 4; ++g) {
                cp16(ab + so[g],         qp + nxt*64 + g*8);
                cp16(ab + 32768 + so[g], kp + nxt*64 + g*8);
            }
            CP_COMMIT();
        }
        if (!wskip) {
            const uint32_t cb = base + (it & 1)*16384;
            mma_chunk(cb, cb + 32768, m0, n0w, lane, c);
        }
    }

    float* dst = g_att_part + (size_t)kc*(4096*256) + (size_t)(b*256 + t0)*256;
    const int r0 = m0 + (lane >> 2);
    const int c0 = n0c + n0w + (lane & 3)*2;
    #pragma unroll
    for (int mt = 0; mt < 2; ++mt)
        #pragma unroll
        for (int n8 = 0; n8 < 8; ++n8) {
            float* p = dst + (size_t)(r0 + mt*16)*256 + c0 + n8*8;
            *(float2*)p           = make_float2(c[mt][n8][0], c[mt][n8][1]);
            *(float2*)(p + 8*256) = make_float2(c[mt][n8][2], c[mt][n8][3]);
        }
}

// ---------------------------------------------------------------------------
// Kernel 3: reduce partials, mask, softmax; emit P' = P + I as fp16.
// The +I on the diagonal folds the residual add (out = P@V + V = (P+I)@V)
// into the GEMM, deleting the buffer read in out_mma.
// ---------------------------------------------------------------------------
__global__ __launch_bounds__(256) void softmax_kernel() {
    const int wid = threadIdx.x >> 5, lane = threadIdx.x & 31;
    const int row = blockIdx.x*8 + wid;   // b*256 + t
    const int t = row & 255;
    float4 a[2];
    #pragma unroll
    for (int j2 = 0; j2 < 2; ++j2) {
        float4 s = make_float4(0.f, 0.f, 0.f, 0.f);
        #pragma unroll
        for (int p = 0; p < KCH; ++p) {
            const float4 d = *(const float4*)(g_att_part + (size_t)p*(4096*256)
                                              + (size_t)row*256 + (j2*32 + lane)*4);
            s.x += d.x; s.y += d.y; s.z += d.z; s.w += d.w;
        }
        a[j2] = s;
    }
    float m = -1e30f;
    #pragma unroll
    for (int j2 = 0; j2 < 2; ++j2) {
        const int c0 = (j2*32 + lane)*4;
        float* e = &a[j2].x;
        #pragma unroll
        for (int q = 0; q < 4; ++q) {
            e[q] = (c0 + q <= t) ? e[q] : -1e30f;
            m = fmaxf(m, e[q]);
        }
    }
    #pragma unroll
    for (int o = 16; o; o >>= 1) m = fmaxf(m, __shfl_xor_sync(0xffffffffu, m, o));
    float ssum = 0.f;
    #pragma unroll
    for (int j2 = 0; j2 < 2; ++j2) {
        const int c0 = (j2*32 + lane)*4;
        float* e = &a[j2].x;
        #pragma unroll
        for (int q = 0; q < 4; ++q) {
            e[q] = (c0 + q <= t) ? __expf(e[q] - m) : 0.f;
            ssum += e[q];
        }
    }
    #pragma unroll
    for (int o = 16; o; o >>= 1) ssum += __shfl_xor_sync(0xffffffffu, ssum, o);
    const float inv = 1.f / ssum;
    #pragma unroll
    for (int j2 = 0; j2 < 2; ++j2) {
        const int c0 = (j2*32 + lane)*4;
        float p0 = a[j2].x*inv + ((c0     == t) ? 1.f : 0.f);
        float p1 = a[j2].y*inv + ((c0 + 1 == t) ? 1.f : 0.f);
        float p2 = a[j2].z*inv + ((c0 + 2 == t) ? 1.f : 0.f);
        float p3 = a[j2].w*inv + ((c0 + 3 == t) ? 1.f : 0.f);
        uint2 u;
        u.x = h2u(__floats2half2_rn(p0, p1));
        u.y = h2u(__floats2half2_rn(p2, p3));
        *(uint2*)(g_ph + (size_t)row*256 + c0) = u;
    }
}

// ---------------------------------------------------------------------------
// Kernel 4: out = (P+I) @ V^T. CTA = (b, st): M=256 t, N=128 s, K=256.
// ALL operands (P' 128KB + V 68KB) loaded in ONE cp.async burst -> zero
// mainloop barriers. Warp map wm={0,1,2,3,7,6,5,4}[wid&7]; warp wm runs
// chunks ic < wm/2+1 (P' zero beyond -> exact) and finishes early.
// Pure-store epilogue (no buffer read). 512 threads, grid 400.
// smem: P[4]x32KB | V[4]x17408B = 200704 B.
// ---------------------------------------------------------------------------
#define OPB 32768u
#define OVB 17408u
#define OFF_V 131072u
__global__ __launch_bounds__(512) void out_mma(float* __restrict__ out) {
    extern __shared__ __align__(128) char sm[];
    const int b = blockIdx.x / 25, st = blockIdx.x % 25;
    const int tid = threadIdx.x, lane = tid & 31, wid = tid >> 5;
    const int w7 = wid & 7;
    const int wm = (w7 < 4) ? w7 : (11 - w7);     // {0,1,2,3,7,6,5,4}
    const int m0 = wm * 32, n0w = (wid >> 3) * 64;
    const int nc = wm/2 + 1;                      // causal chunk bound
    const uint32_t base = smem_u32(sm);

    float c[2][8][4];
    #pragma unroll
    for (int i = 0; i < 2; ++i)
        #pragma unroll
        for (int j = 0; j < 8; ++j)
            #pragma unroll
            for (int e = 0; e < 4; ++e) c[i][j][e] = 0.f;

    // P: prow = tid/2 (0..255), half ph = tid&1; 4 cp16 per chunk
    const int prow = tid >> 1, ph = tid & 1;
    const __half* ap = g_ph + (size_t)(b*256 + prow)*256 + ph*32;
    uint32_t soP[4];
    #pragma unroll
    for (int g = 0; g < 4; ++g) soP[g] = SW128((uint32_t)(prow*128 + ph*64 + g*16));

    // V: vrow = tid/8 (0..63), seg = tid&7; 2 cp16 per chunk
    const int vrow = tid >> 3, seg = tid & 7;
    const __half* vp = g_vh + (size_t)(b*256 + vrow)*SS + st*128 + seg*16;
    const uint32_t soV = (uint32_t)(vrow*(VSTR*2) + seg*32);

    // one burst: everything
    #pragma unroll
    for (int ic = 0; ic < 4; ++ic) {
        #pragma unroll
        for (int g = 0; g < 4; ++g)
            cp16(base + ic*OPB + soP[g], ap + ic*64 + g*8);
        const __half* vs = vp + (size_t)ic*64*SS;
        cp16(base + OFF_V + ic*OVB + soV,      vs);
        cp16(base + OFF_V + ic*OVB + soV + 16, vs + 8);
    }
    CP_COMMIT();
    CP_WAIT0();
    __syncthreads();

    // barrier-free mainloop; warps finish early per causal bound
    for (int ic = 0; ic < nc; ++ic)
        mma_chunk_bt(base + (uint32_t)ic*OPB,
                     base + OFF_V + (uint32_t)ic*OVB, m0, n0w, lane, c);

    const int r0 = m0 + (lane >> 2);
    const int sc0 = n0w + (lane & 3)*2;
    const int soff = st*NSTRIDE;
    #pragma unroll
    for (int mt = 0; mt < 2; ++mt) {
        const int tA = r0 + mt*16;
        const int gA = row_base(b, tA)     + soff;
        const int gB = row_base(b, tA + 8) + soff;
        #pragma unroll
        for (int n8 = 0; n8 < 8; ++n8) {
            const int sc = sc0 + n8*8;
            *(float2*)(out + gA + sc) = make_float2(c[mt][n8][0], c[mt][n8][1]);
            *(float2*)(out + gB + sc) = make_float2(c[mt][n8][2], c[mt][n8][3]);
        }
    }
}

// ---------------------------------------------------------------------------
#define ATT_SMEM 65536
#define OUT_SMEM 200704

extern "C" void kernel_launch(void* const* d_in, const int* in_sizes, int n_in,
                              void* d_out, int out_size) {
    const float* q = (const float*)d_in[0];
    const float* k = (const float*)d_in[1];
    const float* v = (const float*)d_in[2];
    float* out = (float*)d_out;

    cudaFuncSetAttribute(att_mma, cudaFuncAttributeMaxDynamicSharedMemorySize, ATT_SMEM);
    cudaFuncSetAttribute(out_mma, cudaFuncAttributeMaxDynamicSharedMemorySize, OUT_SMEM);

    prep_qk<<<BB*CH, 160>>>(q, k, v);
    att_mma<<<KCH*BB*3, 256, ATT_SMEM>>>();
    softmax_kernel<<<BB*CH/8, 256>>>();
    out_mma<<<BB*NN, 512, OUT_SMEM>>>(out);
}

// round 13
// speedup vs baseline: 1.2665x; 1.0264x over previous
#include <cuda_runtime.h>
#include <cuda_fp16.h>
#include <cstdint>

#define BB 16
#define NN 25
#define WW 128
#define CH 256              // c*h
#define SS 3200             // n*w
#define BSTRIDE 819200
#define CSTRIDE 51200
#define NSTRIDE 2048
#define KCH 3               // K-split chunks in att (17/17/16 x 64)

// Scratch (device globals). Zero-init relied upon: g_att_part regions skipped
// by every launch stay 0 (softmax masks them anyway).
__device__ float g_att_part[KCH*BB*CH*CH];        // 12.6 MB partial logits
__device__ __half g_qh[BB*CH*SS];                 // normalized Q fp16 [row][s]
__device__ __half g_kh[BB*CH*SS];                 // normalized K fp16 [row][s]
__device__ __half g_vh[BB*CH*SS];                 // V fp16 [row][s]
__device__ __half g_ph[BB*CH*CH];                 // P + I (fp16), zeros above diag

__device__ __forceinline__ int row_base(int b, int t) {
    return b*BSTRIDE + (t >> 4)*CSTRIDE + (t & 15)*WW;
}

#define SW128(x) ((x) ^ (((x) >> 3) & 0x70))

__device__ __forceinline__ uint32_t smem_u32(const void* p) {
    uint32_t a;
    asm("{ .reg .u64 t; cvta.to.shared.u64 t, %1; cvt.u32.u64 %0, t; }" : "=r"(a) : "l"(p));
    return a;
}
__device__ __forceinline__ void cp16(uint32_t dst, const void* src) {
    asm volatile("cp.async.cg.shared.global [%0], [%1], 16;"
                 :: "r"(dst), "l"(__cvta_generic_to_global(src)));
}
#define CP_COMMIT() asm volatile("cp.async.commit_group;" ::: "memory")
#define CP_WAIT0()  asm volatile("cp.async.wait_group 0;" ::: "memory")
#define CP_WAIT1()  asm volatile("cp.async.wait_group 1;" ::: "memory")

__device__ __forceinline__ void ldsm_x4(uint32_t& r0, uint32_t& r1,
                                        uint32_t& r2, uint32_t& r3, uint32_t addr) {
    asm volatile("ldmatrix.sync.aligned.m8n8.x4.shared.b16 {%0,%1,%2,%3}, [%4];"
                 : "=r"(r0), "=r"(r1), "=r"(r2), "=r"(r3) : "r"(addr));
}
__device__ __forceinline__ void ldsm_x4t(uint32_t& r0, uint32_t& r1,
                                         uint32_t& r2, uint32_t& r3, uint32_t addr) {
    asm volatile("ldmatrix.sync.aligned.m8n8.x4.trans.shared.b16 {%0,%1,%2,%3}, [%4];"
                 : "=r"(r0), "=r"(r1), "=r"(r2), "=r"(r3) : "r"(addr));
}
__device__ __forceinline__ void mma16816(float* c, const uint32_t* a,
                                         uint32_t b0, uint32_t b1) {
    asm volatile(
        "mma.sync.aligned.m16n8k16.row.col.f32.f16.f16.f32 "
        "{%0,%1,%2,%3}, {%4,%5,%6,%7}, {%8,%9}, {%0,%1,%2,%3};"
        : "+f"(c[0]), "+f"(c[1]), "+f"(c[2]), "+f"(c[3])
        : "r"(a[0]), "r"(a[1]), "r"(a[2]), "r"(a[3]), "r"(b0), "r"(b1));
}
__device__ __forceinline__ uint32_t h2u(__half2 h) {
    return *reinterpret_cast<uint32_t*>(&h);
}

// One 64-wide K chunk, both operands SW128-swizzled [row][64 halves].
__device__ __forceinline__ void mma_chunk(uint32_t aSm, uint32_t bSm,
                                          int m0, int n0, int lane,
                                          float c[2][8][4]) {
    const int lar = lane & 15;
    const int lak = (lane >> 4) * 16;
    const int lbr = (lane & 7) | ((lane >> 4) << 3);
    const int lbk = ((lane >> 3) & 1) * 16;
    #pragma unroll
    for (int ks = 0; ks < 4; ++ks) {
        const int kb = ks * 32;
        uint32_t a[2][4];
        #pragma unroll
        for (int mt = 0; mt < 2; ++mt)
            ldsm_x4(a[mt][0], a[mt][1], a[mt][2], a[mt][3],
                    aSm + SW128((uint32_t)((m0 + mt*16 + lar)*128 + kb + lak)));
        #pragma unroll
        for (int np = 0; np < 4; ++np) {
            uint32_t b0, b1, b2, b3;
            ldsm_x4(b0, b1, b2, b3,
                    bSm + SW128((uint32_t)((n0 + np*16 + lbr)*128 + kb + lbk)));
            mma16816(c[0][np*2    ], a[0], b0, b1);
            mma16816(c[0][np*2 + 1], a[0], b2, b3);
            mma16816(c[1][np*2    ], a[1], b0, b1);
            mma16816(c[1][np*2 + 1], a[1], b2, b3);
        }
    }
}

// One 64-deep K chunk; A = P chunk (SW128 128B rows), B = V chunk natural
// [r=k 64 rows][s=n 128 halves], 272B row stride (conflict-free ldsm.trans).
#define VSTR 136
__device__ __forceinline__ void mma_chunk_bt(uint32_t aSm, uint32_t vSm,
                                             int m0, int n0, int lane,
                                             float c[2][8][4]) {
    const int lar = lane & 15;
    const int lak = (lane >> 4) * 16;
    const int vr = lane & 15;
    const int vs = (lane >> 4) * 8;
    #pragma unroll
    for (int ks = 0; ks < 4; ++ks) {
        uint32_t a[2][4];
        #pragma unroll
        for (int mt = 0; mt < 2; ++mt)
            ldsm_x4(a[mt][0], a[mt][1], a[mt][2], a[mt][3],
                    aSm + SW128((uint32_t)((m0 + mt*16 + lar)*128 + ks*32 + lak)));
        #pragma unroll
        for (int np = 0; np < 4; ++np) {
            uint32_t b0, b1, b2, b3;
            ldsm_x4t(b0, b1, b2, b3,
                     vSm + (uint32_t)((ks*16 + vr)*(VSTR*2) + (n0 + np*16 + vs)*2));
            mma16816(c[0][np*2    ], a[0], b0, b1);
            mma16816(c[0][np*2 + 1], a[0], b2, b3);
            mma16816(c[1][np*2    ], a[1], b0, b1);
            mma16816(c[1][np*2 + 1], a[1], b2, b3);
        }
    }
}

// ---------------------------------------------------------------------------
// Kernel 1: fused L2-norm + normalize + fp16 pack for Q,K; fp16 convert of V.
// ---------------------------------------------------------------------------
__global__ __launch_bounds__(160) void prep_qk(const float* __restrict__ q,
                                               const float* __restrict__ k,
                                               const float* __restrict__ v) {
    __shared__ float rq[8], rk[8];
    const int row = blockIdx.x;
    const int b = row >> 8, t = row & 255;
    const int tid = threadIdx.x, lane = tid & 31, w = tid >> 5;
    const int base = row_base(b, t);
    float4 qv[5], kv[5];
    float sq = 0.f, sk = 0.f;
    #pragma unroll
    for (int g = 0; g < 5; ++g) {
        const int s = (tid + 160*g) * 4;
        const int a = base + (s >> 7)*NSTRIDE + (s & 127);
        qv[g] = *(const float4*)(q + a);
        kv[g] = *(const float4*)(k + a);
        sq += qv[g].x*qv[g].x + qv[g].y*qv[g].y + qv[g].z*qv[g].z + qv[g].w*qv[g].w;
        sk += kv[g].x*kv[g].x + kv[g].y*kv[g].y + kv[g].z*kv[g].z + kv[g].w*kv[g].w;
    }
    #pragma unroll
    for (int g = 0; g < 5; ++g) {
        const int s = (tid + 160*g) * 4;
        const int a = base + (s >> 7)*NSTRIDE + (s & 127);
        const float4 vv = *(const float4*)(v + a);
        uint2 uv;
        uv.x = h2u(__floats2half2_rn(vv.x, vv.y));
        uv.y = h2u(__floats2half2_rn(vv.z, vv.w));
        *(uint2*)(g_vh + (size_t)row*SS + s) = uv;
    }
    #pragma unroll
    for (int o = 16; o; o >>= 1) {
        sq += __shfl_xor_sync(0xffffffffu, sq, o);
        sk += __shfl_xor_sync(0xffffffffu, sk, o);
    }
    if (lane == 0) { rq[w] = sq; rk[w] = sk; }
    __syncthreads();
    sq = rq[0] + rq[1] + rq[2] + rq[3] + rq[4];
    sk = rk[0] + rk[1] + rk[2] + rk[3] + rk[4];
    const float iq = 1.f / fmaxf(sqrtf(sq), 1e-12f);
    const float ik = 1.f / fmaxf(sqrtf(sk), 1e-12f);
    #pragma unroll
    for (int g = 0; g < 5; ++g) {
        const int s = (tid + 160*g) * 4;
        uint2 uq, uk;
        uq.x = h2u(__floats2half2_rn(qv[g].x*iq, qv[g].y*iq));
        uq.y = h2u(__floats2half2_rn(qv[g].z*iq, qv[g].w*iq));
        uk.x = h2u(__floats2half2_rn(kv[g].x*ik, kv[g].y*ik));
        uk.y = h2u(__floats2half2_rn(kv[g].z*ik, kv[g].w*ik));
        *(uint2*)(g_qh + (size_t)row*SS + s) = uq;
        *(uint2*)(g_kh + (size_t)row*SS + s) = uk;
    }
}

// ---------------------------------------------------------------------------
// Kernel 2: att partial logits, cp.async double-buffered, fp16 mma.sync.
// CTA = (kc, b, tile), tile in {(mh0,nh0),(mh1,nh0),(mh1,nh1)}. Grid 144.
// Diagonal tiles: warps fully above the diagonal skip all mma (zeros stored;
// softmax masks that region).
// ---------------------------------------------------------------------------
__global__ __launch_bounds__(256, 2) void att_mma() {
    extern __shared__ __align__(128) char sm[];
    int idx = blockIdx.x;
    const int kc = idx / 48; idx %= 48;
    const int b = idx / 3, tt = idx % 3;
    const int t0  = (tt > 0)  ? 128 : 0;
    const int n0c = (tt == 2) ? 128 : 0;
    const int nch = (kc == 2) ? 16 : 17;
    const int sb  = kc * 17 * 64;
    const int tid = threadIdx.x, lane = tid & 31, wid = tid >> 5;
    const int m0 = (wid & 3) * 32, n0w = (wid >> 2) * 64;
    const bool wskip = (t0 == n0c) && (n0w > m0 + 31);
    const uint32_t base = smem_u32(sm);

    float c[2][8][4];
    #pragma unroll
    for (int i = 0; i < 2; ++i)
        #pragma unroll
        for (int j = 0; j < 8; ++j)
            #pragma unroll
            for (int e = 0; e < 4; ++e) c[i][j][e] = 0.f;

    const int row = tid >> 1, hf = tid & 1;
    const __half* qp = g_qh + (size_t)(b*256 + t0  + row)*SS + sb + hf*32;
    const __half* kp = g_kh + (size_t)(b*256 + n0c + row)*SS + sb + hf*32;
    uint32_t so[4];
    #pragma unroll
    for (int g = 0; g < 4; ++g) so[g] = SW128((uint32_t)(row*128 + hf*64 + g*16));

    #pragma unroll
    for (int g = 0; g < 4; ++g) {
        cp16(base + so[g],         qp + g*8);
        cp16(base + 32768 + so[g], kp + g*8);
    }
    CP_COMMIT();

    for (int it = 0; it < nch; ++it) {
        CP_WAIT0();
        __syncthreads();
        const int nxt = it + 1;
        if (nxt < nch) {
            const uint32_t ab = base + (nxt & 1)*16384;
            #pragma unroll
            for (int g = 0; g < 4; ++g) {
                cp16(ab + so[g],         qp + nxt*64 + g*8);
                cp16(ab + 32768 + so[g], kp + nxt*64 + g*8);
            }
            CP_COMMIT();
        }
        if (!wskip) {
            const uint32_t cb = base + (it & 1)*16384;
            mma_chunk(cb, cb + 32768, m0, n0w, lane, c);
        }
    }

    float* dst = g_att_part + (size_t)kc*(4096*256) + (size_t)(b*256 + t0)*256;
    const int r0 = m0 + (lane >> 2);
    const int c0 = n0c + n0w + (lane & 3)*2;
    #pragma unroll
    for (int mt = 0; mt < 2; ++mt)
        #pragma unroll
        for (int n8 = 0; n8 < 8; ++n8) {
            float* p = dst + (size_t)(r0 + mt*16)*256 + c0 + n8*8;
            *(float2*)p           = make_float2(c[mt][n8][0], c[mt][n8][1]);
            *(float2*)(p + 8*256) = make_float2(c[mt][n8][2], c[mt][n8][3]);
        }
}

// ---------------------------------------------------------------------------
// Kernel 3: reduce partials, mask, softmax; emit P' = P + I as fp16.
// ---------------------------------------------------------------------------
__global__ __launch_bounds__(256) void softmax_kernel() {
    const int wid = threadIdx.x >> 5, lane = threadIdx.x & 31;
    const int row = blockIdx.x*8 + wid;   // b*256 + t
    const int t = row & 255;
    float4 a[2];
    #pragma unroll
    for (int j2 = 0; j2 < 2; ++j2) {
        float4 s = make_float4(0.f, 0.f, 0.f, 0.f);
        #pragma unroll
        for (int p = 0; p < KCH; ++p) {
            const float4 d = *(const float4*)(g_att_part + (size_t)p*(4096*256)
                                              + (size_t)row*256 + (j2*32 + lane)*4);
            s.x += d.x; s.y += d.y; s.z += d.z; s.w += d.w;
        }
        a[j2] = s;
    }
    float m = -1e30f;
    #pragma unroll
    for (int j2 = 0; j2 < 2; ++j2) {
        const int c0 = (j2*32 + lane)*4;
        float* e = &a[j2].x;
        #pragma unroll
        for (int q = 0; q < 4; ++q) {
            e[q] = (c0 + q <= t) ? e[q] : -1e30f;
            m = fmaxf(m, e[q]);
        }
    }
    #pragma unroll
    for (int o = 16; o; o >>= 1) m = fmaxf(m, __shfl_xor_sync(0xffffffffu, m, o));
    float ssum = 0.f;
    #pragma unroll
    for (int j2 = 0; j2 < 2; ++j2) {
        const int c0 = (j2*32 + lane)*4;
        float* e = &a[j2].x;
        #pragma unroll
        for (int q = 0; q < 4; ++q) {
            e[q] = (c0 + q <= t) ? __expf(e[q] - m) : 0.f;
            ssum += e[q];
        }
    }
    #pragma unroll
    for (int o = 16; o; o >>= 1) ssum += __shfl_xor_sync(0xffffffffu, ssum, o);
    const float inv = 1.f / ssum;
    #pragma unroll
    for (int j2 = 0; j2 < 2; ++j2) {
        const int c0 = (j2*32 + lane)*4;
        float p0 = a[j2].x*inv + ((c0     == t) ? 1.f : 0.f);
        float p1 = a[j2].y*inv + ((c0 + 1 == t) ? 1.f : 0.f);
        float p2 = a[j2].z*inv + ((c0 + 2 == t) ? 1.f : 0.f);
        float p3 = a[j2].w*inv + ((c0 + 3 == t) ? 1.f : 0.f);
        uint2 u;
        u.x = h2u(__floats2half2_rn(p0, p1));
        u.y = h2u(__floats2half2_rn(p2, p3));
        *(uint2*)(g_ph + (size_t)row*256 + c0) = u;
    }
}

// ---------------------------------------------------------------------------
// Kernel 4: out = (P+I) @ V^T. CTA = (b, st): M=256 t, N=128 s, K=256.
// Two-group cp.async pipeline: group0 = chunk 0 (half the MMA work), group1 =
// chunks 1-3; compute of chunk 0 hides group1's load. P' chunk ic loaded only
// for rows t >= 64*ic (rest is zero and never read -> 128KB->80KB).
// Warp map wm={0,1,2,3,7,6,5,4}[wid&7]; warp wm runs chunks ic < wm/2+1.
// Pure-store epilogue. 512 threads, grid 400. smem 200704 B.
// ---------------------------------------------------------------------------
#define OPB 32768u
#define OVB 17408u
#define OFF_V 131072u
__global__ __launch_bounds__(512) void out_mma(float* __restrict__ out) {
    extern __shared__ __align__(128) char sm[];
    const int b = blockIdx.x / 25, st = blockIdx.x % 25;
    const int tid = threadIdx.x, lane = tid & 31, wid = tid >> 5;
    const int w7 = wid & 7;
    const int wm = (w7 < 4) ? w7 : (11 - w7);     // {0,1,2,3,7,6,5,4}
    const int m0 = wm * 32, n0w = (wid >> 3) * 64;
    const int nc = wm/2 + 1;                      // causal chunk bound
    const uint32_t base = smem_u32(sm);

    float c[2][8][4];
    #pragma unroll
    for (int i = 0; i < 2; ++i)
        #pragma unroll
        for (int j = 0; j < 8; ++j)
            #pragma unroll
            for (int e = 0; e < 4; ++e) c[i][j][e] = 0.f;

    // P: prow = tid/2 (0..255), half ph = tid&1; 4 cp16 per chunk
    const int prow = tid >> 1, ph = tid & 1;
    const __half* ap = g_ph + (size_t)(b*256 + prow)*256 + ph*32;
    uint32_t soP[4];
    #pragma unroll
    for (int g = 0; g < 4; ++g) soP[g] = SW128((uint32_t)(prow*128 + ph*64 + g*16));

    // V: vrow = tid/8 (0..63), seg = tid&7; 2 cp16 per chunk
    const int vrow = tid >> 3, seg = tid & 7;
    const __half* vp = g_vh + (size_t)(b*256 + vrow)*SS + st*128 + seg*16;
    const uint32_t soV = (uint32_t)(vrow*(VSTR*2) + seg*32);

    // group 0: chunk 0 (P all rows + V)
    #pragma unroll
    for (int g = 0; g < 4; ++g) cp16(base + soP[g], ap + g*8);
    cp16(base + OFF_V + soV,      vp);
    cp16(base + OFF_V + soV + 16, vp + 8);
    CP_COMMIT();

    // group 1: chunks 1-3 (P only for rows >= 64*ic; rest zero & unread)
    #pragma unroll
    for (int ic = 1; ic < 4; ++ic) {
        if (prow >= ic*64) {
            #pragma unroll
            for (int g = 0; g < 4; ++g)
                cp16(base + ic*OPB + soP[g], ap + ic*64 + g*8);
        }
        const __half* vs = vp + (size_t)ic*64*SS;
        cp16(base + OFF_V + ic*OVB + soV,      vs);
        cp16(base + OFF_V + ic*OVB + soV + 16, vs + 8);
    }
    CP_COMMIT();

    CP_WAIT1();
    __syncthreads();
    mma_chunk_bt(base, base + OFF_V, m0, n0w, lane, c);   // chunk 0 (all warps)

    CP_WAIT0();
    __syncthreads();
    for (int ic = 1; ic < nc; ++ic)                       // early finish per warp
        mma_chunk_bt(base + (uint32_t)ic*OPB,
                     base + OFF_V + (uint32_t)ic*OVB, m0, n0w, lane, c);

    const int r0 = m0 + (lane >> 2);
    const int sc0 = n0w + (lane & 3)*2;
    const int soff = st*NSTRIDE;
    #pragma unroll
    for (int mt = 0; mt < 2; ++mt) {
        const int tA = r0 + mt*16;
        const int gA = row_base(b, tA)     + soff;
        const int gB = row_base(b, tA + 8) + soff;
        #pragma unroll
        for (int n8 = 0; n8 < 8; ++n8) {
            const int sc = sc0 + n8*8;
            *(float2*)(out + gA + sc) = make_float2(c[mt][n8][0], c[mt][n8][1]);
            *(float2*)(out + gB + sc) = make_float2(c[mt][n8][2], c[mt][n8][3]);
        }
    }
}

// ---------------------------------------------------------------------------
#define ATT_SMEM 65536
#define OUT_SMEM 200704

extern "C" void kernel_launch(void* const* d_in, const int* in_sizes, int n_in,
                              void* d_out, int out_size) {
    const float* q = (const float*)d_in[0];
    const float* k = (const float*)d_in[1];
    const float* v = (const float*)d_in[2];
    float* out = (float*)d_out;

    cudaFuncSetAttribute(att_mma, cudaFuncAttributeMaxDynamicSharedMemorySize, ATT_SMEM);
    cudaFuncSetAttribute(out_mma, cudaFuncAttributeMaxDynamicSharedMemorySize, OUT_SMEM);

    prep_qk<<<BB*CH, 160>>>(q, k, v);
    att_mma<<<KCH*BB*3, 256, ATT_SMEM>>>();
    softmax_kernel<<<BB*CH/8, 256>>>();
    out_mma<<<BB*NN, 512, OUT_SMEM>>>(out);
}